// round 2
// baseline (speedup 1.0000x reference)
#include <cuda_runtime.h>

#define B     16
#define S     1024
#define HID   768
#define NH    8
#define HD    96
#define OUTF  4
#define NSCHUNK 4
#define SCHUNK (S / NSCHUNK)   // 256

// Scratch (no device allocation allowed)
__device__ float g_q0[B * HID];                       // q at position 0
__device__ float g_u[B * NH * HID];                   // u[b,h,:] = Wk_h @ q0_h
__device__ float g_scores[B * NH * S];                // scores -> probs (in place)
__device__ float g_wpart[B * NH * NSCHUNK * HID];     // partial prob-weighted X sums
__device__ float g_ctx[B * HID];                      // ctx at position 0

// ---------------------------------------------------------------------------
// Kernel 1: q0[b,:] = X[b,0,:] @ Wq + bq          grid(B), block(256)
// ---------------------------------------------------------------------------
__global__ void __launch_bounds__(256) k_q0(const float* __restrict__ X,
                                            const float* __restrict__ Wq,
                                            const float* __restrict__ bq) {
    int b = blockIdx.x;
    __shared__ float sx[HID];
    const float* xrow = X + (size_t)b * S * HID;  // s = 0
    for (int i = threadIdx.x; i < HID; i += 256) sx[i] = xrow[i];
    __syncthreads();
    int j = threadIdx.x;
    float a0 = bq[j], a1 = bq[j + 256], a2 = bq[j + 512];
    for (int i = 0; i < HID; i++) {
        float x = sx[i];
        const float* w = Wq + (size_t)i * HID + j;
        a0 += x * w[0];
        a1 += x * w[256];
        a2 += x * w[512];
    }
    g_q0[b * HID + j]       = a0;
    g_q0[b * HID + j + 256] = a1;
    g_q0[b * HID + j + 512] = a2;
}

// ---------------------------------------------------------------------------
// Kernel 2: u[b,h,i] = sum_d Wk[i, h*96+d] * q0[b, h*96+d]
// grid(B*NH), block(256).  (bk drops out: constant shift per (b,h) -> softmax invariant)
// ---------------------------------------------------------------------------
__global__ void __launch_bounds__(256) k_u(const float* __restrict__ Wk) {
    int bh = blockIdx.x;
    int b = bh >> 3, h = bh & 7;
    __shared__ float4 sq[HD / 4];
    if (threadIdx.x < HD / 4)
        sq[threadIdx.x] = ((const float4*)(g_q0 + b * HID + h * HD))[threadIdx.x];
    __syncthreads();
    for (int i = threadIdx.x; i < HID; i += 256) {
        const float4* wr = (const float4*)(Wk + (size_t)i * HID + h * HD);
        float acc = 0.f;
#pragma unroll
        for (int d = 0; d < HD / 4; d++) {
            float4 w = wr[d], q = sq[d];
            acc += w.x * q.x + w.y * q.y + w.z * q.z + w.w * q.w;
        }
        g_u[bh * HID + i] = acc;
    }
}

// ---------------------------------------------------------------------------
// Kernel 3: scores[b,h,s] = (X[b,s,:] . u[b,h,:]) / sqrt(96) + mask_add(b,s)
// grid(S/32, B), block(256) = 8 warps; each warp does 4 rows, all 8 heads.
// ---------------------------------------------------------------------------
__global__ void __launch_bounds__(256) k_scores(const float* __restrict__ X,
                                                const float* __restrict__ mask) {
    int b = blockIdx.y;
    int s_base = blockIdx.x * 32;
    __shared__ float4 su[NH][HID / 4];   // 24 KB
    const float4* u4 = (const float4*)(g_u + (size_t)b * NH * HID);
    for (int i = threadIdx.x; i < NH * HID / 4; i += 256) (&su[0][0])[i] = u4[i];
    __syncthreads();

    int warp = threadIdx.x >> 5, lane = threadIdx.x & 31;
    const float scale = 0.1020620726159658f;  // 1/sqrt(96)

    for (int r = 0; r < 4; r++) {
        int s = s_base + warp * 4 + r;
        const float4* xr = (const float4*)(X + ((size_t)b * S + s) * HID);
        float acc[NH];
#pragma unroll
        for (int h = 0; h < NH; h++) acc[h] = 0.f;
#pragma unroll
        for (int k = 0; k < HID / 4 / 32; k++) {   // 6 iterations
            float4 x = xr[lane + 32 * k];
#pragma unroll
            for (int h = 0; h < NH; h++) {
                float4 u = su[h][lane + 32 * k];
                acc[h] += x.x * u.x + x.y * u.y + x.z * u.z + x.w * u.w;
            }
        }
#pragma unroll
        for (int h = 0; h < NH; h++)
#pragma unroll
            for (int o = 16; o > 0; o >>= 1)
                acc[h] += __shfl_xor_sync(0xffffffffu, acc[h], o);

        float madd = (1.0f - mask[b * S + s]) * -10000.0f;
#pragma unroll
        for (int h = 0; h < NH; h++)
            if (lane == h) g_scores[((b * NH + h) * S) + s] = acc[h] * scale + madd;
    }
}

// ---------------------------------------------------------------------------
// Kernel 4: softmax over S per (b,h), in place.  grid(B*NH), block(256)
// ---------------------------------------------------------------------------
__global__ void __launch_bounds__(256) k_softmax() {
    int bh = blockIdx.x;
    float4* sc = ((float4*)g_scores) + (size_t)bh * (S / 4);
    __shared__ float red[8];
    __shared__ float bcast;
    int t = threadIdx.x;
    float4 v = sc[t];

    float m = fmaxf(fmaxf(v.x, v.y), fmaxf(v.z, v.w));
#pragma unroll
    for (int o = 16; o > 0; o >>= 1) m = fmaxf(m, __shfl_xor_sync(0xffffffffu, m, o));
    if ((t & 31) == 0) red[t >> 5] = m;
    __syncthreads();
    if (t == 0) {
        float mm = red[0];
        for (int i = 1; i < 8; i++) mm = fmaxf(mm, red[i]);
        bcast = mm;
    }
    __syncthreads();
    m = bcast;

    v.x = __expf(v.x - m); v.y = __expf(v.y - m);
    v.z = __expf(v.z - m); v.w = __expf(v.w - m);
    float ssum = v.x + v.y + v.z + v.w;
#pragma unroll
    for (int o = 16; o > 0; o >>= 1) ssum += __shfl_xor_sync(0xffffffffu, ssum, o);
    if ((t & 31) == 0) red[t >> 5] = ssum;
    __syncthreads();
    if (t == 0) {
        float s2 = red[0];
        for (int i = 1; i < 8; i++) s2 += red[i];
        bcast = s2;
    }
    __syncthreads();
    float inv = 1.0f / bcast;
    v.x *= inv; v.y *= inv; v.z *= inv; v.w *= inv;
    sc[t] = v;
}

// ---------------------------------------------------------------------------
// Kernel 5: partial w[b,h,i] = sum_{s in chunk} probs[b,h,s] * X[b,s,i]
// grid(B, HID/192, NSCHUNK), block(192). Deterministic (no atomics).
// ---------------------------------------------------------------------------
__global__ void __launch_bounds__(192) k_wsum(const float* __restrict__ X) {
    int b = blockIdx.x, cc = blockIdx.y, scnk = blockIdx.z;
    int i = cc * 192 + threadIdx.x;
    __shared__ float sp[SCHUNK][NH];   // [s][h] layout -> float4 broadcast reads
    for (int idx = threadIdx.x; idx < SCHUNK * NH; idx += 192) {
        int h = idx / SCHUNK, s = idx % SCHUNK;
        sp[s][h] = g_scores[(size_t)(b * NH + h) * S + scnk * SCHUNK + s];
    }
    __syncthreads();

    float acc[NH];
#pragma unroll
    for (int h = 0; h < NH; h++) acc[h] = 0.f;
    const float* xp = X + ((size_t)b * S + scnk * SCHUNK) * HID + i;
    for (int s = 0; s < SCHUNK; s++) {
        float x = xp[(size_t)s * HID];
        float4 p0 = *(const float4*)&sp[s][0];
        float4 p1 = *(const float4*)&sp[s][4];
        acc[0] += p0.x * x; acc[1] += p0.y * x; acc[2] += p0.z * x; acc[3] += p0.w * x;
        acc[4] += p1.x * x; acc[5] += p1.y * x; acc[6] += p1.z * x; acc[7] += p1.w * x;
    }
#pragma unroll
    for (int h = 0; h < NH; h++)
        g_wpart[(((size_t)(b * NH + h)) * NSCHUNK + scnk) * HID + i] = acc[h];
}

// ---------------------------------------------------------------------------
// Kernel 6: ctx[b, h*96+d] = w[b,h,:] @ Wv[:, h*96+d] + bv   grid(B), block(256)
// ---------------------------------------------------------------------------
__global__ void __launch_bounds__(256) k_ctx(const float* __restrict__ Wv,
                                             const float* __restrict__ bv) {
    int b = blockIdx.x;
    __shared__ float sw[NH * HID];   // 24 KB
    for (int idx = threadIdx.x; idx < NH * HID; idx += 256) {
        int h = idx / HID, i = idx - h * HID;
        size_t base = ((size_t)(b * NH + h)) * NSCHUNK * HID + i;
        float a = 0.f;
        for (int c = 0; c < NSCHUNK; c++) a += g_wpart[base + (size_t)c * HID];
        sw[idx] = a;
    }
    __syncthreads();
    int j = threadIdx.x;
    int h0 = j / HD, h1 = (j + 256) / HD, h2 = (j + 512) / HD;
    float a0 = bv[j], a1 = bv[j + 256], a2 = bv[j + 512];
    for (int i = 0; i < HID; i++) {
        const float* w = Wv + (size_t)i * HID + j;
        a0 += sw[h0 * HID + i] * w[0];
        a1 += sw[h1 * HID + i] * w[256];
        a2 += sw[h2 * HID + i] * w[512];
    }
    g_ctx[b * HID + j]       = a0;
    g_ctx[b * HID + j + 256] = a1;
    g_ctx[b * HID + j + 512] = a2;
}

// ---------------------------------------------------------------------------
// Kernel 7: out[b,j] = relu(ctx[b,:] @ Wo[:,j] + bo[j])   grid(B), block(128)
// ---------------------------------------------------------------------------
__global__ void __launch_bounds__(128) k_out(const float* __restrict__ Wo,
                                             const float* __restrict__ bo,
                                             float* __restrict__ out) {
    int b = blockIdx.x;
    int warp = threadIdx.x >> 5, lane = threadIdx.x & 31;
    float acc = 0.f;
    for (int i = lane; i < HID; i += 32)
        acc += g_ctx[b * HID + i] * Wo[i * OUTF + warp];
#pragma unroll
    for (int o = 16; o > 0; o >>= 1) acc += __shfl_xor_sync(0xffffffffu, acc, o);
    if (lane == 0) out[b * OUTF + warp] = fmaxf(acc + bo[warp], 0.f);
}

// ---------------------------------------------------------------------------
extern "C" void kernel_launch(void* const* d_in, const int* in_sizes, int n_in,
                              void* d_out, int out_size) {
    const float* X    = (const float*)d_in[0];  // hidden_states (B,S,HID)
    const float* mask = (const float*)d_in[1];  // attention_mask (B,S)
    const float* Wq   = (const float*)d_in[2];
    const float* bq   = (const float*)d_in[3];
    const float* Wk   = (const float*)d_in[4];
    // d_in[5] = bk: provably softmax-invariant (constant per (b,h)), unused
    const float* Wv   = (const float*)d_in[6];
    const float* bv   = (const float*)d_in[7];
    const float* Wo   = (const float*)d_in[8];
    const float* bo   = (const float*)d_in[9];
    float* out = (float*)d_out;
    (void)in_sizes; (void)n_in; (void)out_size;

    k_q0<<<B, 256>>>(X, Wq, bq);
    k_u<<<B * NH, 256>>>(Wk);
    dim3 gs(S / 32, B);
    k_scores<<<gs, 256>>>(X, mask);
    k_softmax<<<B * NH, 256>>>();
    dim3 gw(B, HID / 192, NSCHUNK);
    k_wsum<<<gw, 192>>>(X);
    k_ctx<<<B, 256>>>(Wv, bv);
    k_out<<<B, 128>>>(Wo, bo, out);
}

// round 3
// speedup vs baseline: 2.2158x; 2.2158x over previous
#include <cuda_runtime.h>

#define B     16
#define S     1024
#define HID   768
#define NH    8
#define HD    96
#define OUTF  4
#define NSCHUNK 16
#define SCHUNK (S / NSCHUNK)   // 64

// Scratch (no device allocation allowed)
__device__ float g_q0[B * HID];                       // q at position 0
__device__ float g_u[B * NH * HID];                   // u[b,h,:] = Wk_h @ q0_h
__device__ float g_scores[B * NH * S];                // scores -> probs (in place)
__device__ float g_wpart[B * NH * NSCHUNK * HID];     // partial prob-weighted X sums
__device__ float g_ctx[B * HID];                      // ctx at position 0

// ---------------------------------------------------------------------------
// Kernel 1: q0[b,:] = X[b,0,:] @ Wq + bq
// grid(B, 6): each block does a 128-column tile of one batch row; 256 thr =
// 128 j-cols x 2 k-groups of 384 i each, reduced in smem. Wq read once total.
// ---------------------------------------------------------------------------
__global__ void __launch_bounds__(256) k_q0(const float* __restrict__ X,
                                            const float* __restrict__ Wq,
                                            const float* __restrict__ bq) {
    int b = blockIdx.x, jt = blockIdx.y;
    __shared__ float sx[HID];
    __shared__ float part[128];
    const float* xrow = X + (size_t)b * S * HID;  // s = 0
    for (int i = threadIdx.x; i < HID; i += 256) sx[i] = xrow[i];
    __syncthreads();
    int j = threadIdx.x & 127, kg = threadIdx.x >> 7;  // kg in {0,1}
    const float* w = Wq + jt * 128 + j;
    float acc = 0.f;
    int i0 = kg * 384;
#pragma unroll 8
    for (int i = i0; i < i0 + 384; i++) acc += sx[i] * w[(size_t)i * HID];
    if (kg == 1) part[j] = acc;
    __syncthreads();
    if (kg == 0)
        g_q0[b * HID + jt * 128 + j] = acc + part[j] + bq[jt * 128 + j];
}

// ---------------------------------------------------------------------------
// Kernel 2: u[b,h,i] = sum_d Wk[i, h*96+d] * q0[b, h*96+d]   (bk softmax-invariant)
// grid(NH, 6): block (h, i-tile of 128). 128 threads, each thread one i,
// accumulates ALL 16 batches -> Wk read exactly once from DRAM.
// ---------------------------------------------------------------------------
__global__ void __launch_bounds__(128) k_u(const float* __restrict__ Wk) {
    int h = blockIdx.x, it = blockIdx.y;
    int i = it * 128 + threadIdx.x;
    __shared__ float4 sq[B][HD / 4];   // q0[b, h*96 : h*96+96], 6 KB
    for (int idx = threadIdx.x; idx < B * HD / 4; idx += 128) {
        int b = idx / (HD / 4), d4 = idx % (HD / 4);
        sq[b][d4] = ((const float4*)(g_q0 + b * HID + h * HD))[d4];
    }
    __syncthreads();
    const float4* wr = (const float4*)(Wk + (size_t)i * HID + h * HD);
    float acc[B];
#pragma unroll
    for (int b = 0; b < B; b++) acc[b] = 0.f;
#pragma unroll 4
    for (int d4 = 0; d4 < HD / 4; d4++) {
        float4 w = wr[d4];
#pragma unroll
        for (int b = 0; b < B; b++) {
            float4 q = sq[b][d4];
            acc[b] += w.x * q.x + w.y * q.y + w.z * q.z + w.w * q.w;
        }
    }
#pragma unroll
    for (int b = 0; b < B; b++) g_u[(b * NH + h) * HID + i] = acc[b];
}

// ---------------------------------------------------------------------------
// Kernel 3: scores[b,h,s] = (X[b,s,:] . u[b,h,:]) / sqrt(96) + mask_add(b,s)
// grid(S/32, B), block(256) = 8 warps; each warp does 4 rows, all 8 heads.
// ---------------------------------------------------------------------------
__global__ void __launch_bounds__(256) k_scores(const float* __restrict__ X,
                                                const float* __restrict__ mask) {
    int b = blockIdx.y;
    int s_base = blockIdx.x * 32;
    __shared__ float4 su[NH][HID / 4];   // 24 KB
    const float4* u4 = (const float4*)(g_u + (size_t)b * NH * HID);
    for (int i = threadIdx.x; i < NH * HID / 4; i += 256) (&su[0][0])[i] = u4[i];
    __syncthreads();

    int warp = threadIdx.x >> 5, lane = threadIdx.x & 31;
    const float scale = 0.1020620726159658f;  // 1/sqrt(96)

    for (int r = 0; r < 4; r++) {
        int s = s_base + warp * 4 + r;
        const float4* xr = (const float4*)(X + ((size_t)b * S + s) * HID);
        float acc[NH];
#pragma unroll
        for (int h = 0; h < NH; h++) acc[h] = 0.f;
#pragma unroll
        for (int k = 0; k < HID / 4 / 32; k++) {   // 6 iterations
            float4 x = xr[lane + 32 * k];
#pragma unroll
            for (int h = 0; h < NH; h++) {
                float4 u = su[h][lane + 32 * k];
                acc[h] += x.x * u.x + x.y * u.y + x.z * u.z + x.w * u.w;
            }
        }
#pragma unroll
        for (int h = 0; h < NH; h++)
#pragma unroll
            for (int o = 16; o > 0; o >>= 1)
                acc[h] += __shfl_xor_sync(0xffffffffu, acc[h], o);

        float madd = (1.0f - mask[b * S + s]) * -10000.0f;
#pragma unroll
        for (int h = 0; h < NH; h++)
            if (lane == h) g_scores[((b * NH + h) * S) + s] = acc[h] * scale + madd;
    }
}

// ---------------------------------------------------------------------------
// Kernel 4: softmax over S per (b,h), in place.  grid(B*NH), block(256)
// ---------------------------------------------------------------------------
__global__ void __launch_bounds__(256) k_softmax() {
    int bh = blockIdx.x;
    float4* sc = ((float4*)g_scores) + (size_t)bh * (S / 4);
    __shared__ float red[8];
    __shared__ float bcast;
    int t = threadIdx.x;
    float4 v = sc[t];

    float m = fmaxf(fmaxf(v.x, v.y), fmaxf(v.z, v.w));
#pragma unroll
    for (int o = 16; o > 0; o >>= 1) m = fmaxf(m, __shfl_xor_sync(0xffffffffu, m, o));
    if ((t & 31) == 0) red[t >> 5] = m;
    __syncthreads();
    if (t == 0) {
        float mm = red[0];
        for (int i = 1; i < 8; i++) mm = fmaxf(mm, red[i]);
        bcast = mm;
    }
    __syncthreads();
    m = bcast;

    v.x = __expf(v.x - m); v.y = __expf(v.y - m);
    v.z = __expf(v.z - m); v.w = __expf(v.w - m);
    float ssum = v.x + v.y + v.z + v.w;
#pragma unroll
    for (int o = 16; o > 0; o >>= 1) ssum += __shfl_xor_sync(0xffffffffu, ssum, o);
    if ((t & 31) == 0) red[t >> 5] = ssum;
    __syncthreads();
    if (t == 0) {
        float s2 = red[0];
        for (int i = 1; i < 8; i++) s2 += red[i];
        bcast = s2;
    }
    __syncthreads();
    float inv = 1.0f / bcast;
    v.x *= inv; v.y *= inv; v.z *= inv; v.w *= inv;
    sc[t] = v;
}

// ---------------------------------------------------------------------------
// Kernel 5: partial w[b,h,i] = sum_{s in chunk} probs[b,h,s] * X[b,s,i]
// grid(B, NSCHUNK=16), block(192): each thread owns 4 columns (float4),
// so every s-iteration is one LDG.128 + 32 FMA. Deterministic (no atomics).
// ---------------------------------------------------------------------------
__global__ void __launch_bounds__(192) k_wsum(const float* __restrict__ X) {
    int b = blockIdx.x, scnk = blockIdx.y;
    __shared__ float sp[SCHUNK][NH];   // 2 KB, row = 32 B -> float4-aligned
    for (int idx = threadIdx.x; idx < SCHUNK * NH; idx += 192) {
        int h = idx / SCHUNK, s = idx % SCHUNK;
        sp[s][h] = g_scores[(size_t)(b * NH + h) * S + scnk * SCHUNK + s];
    }
    __syncthreads();

    int i4 = threadIdx.x;  // columns 4*i4 .. 4*i4+3
    const float4* xp = (const float4*)(X + ((size_t)b * S + scnk * SCHUNK) * HID) + i4;
    float4 acc[NH];
#pragma unroll
    for (int h = 0; h < NH; h++) acc[h] = make_float4(0.f, 0.f, 0.f, 0.f);

#pragma unroll 4
    for (int s = 0; s < SCHUNK; s++) {
        float4 x = xp[(size_t)s * (HID / 4)];
        float4 p0 = *(const float4*)&sp[s][0];
        float4 p1 = *(const float4*)&sp[s][4];
        acc[0].x += p0.x * x.x; acc[0].y += p0.x * x.y; acc[0].z += p0.x * x.z; acc[0].w += p0.x * x.w;
        acc[1].x += p0.y * x.x; acc[1].y += p0.y * x.y; acc[1].z += p0.y * x.z; acc[1].w += p0.y * x.w;
        acc[2].x += p0.z * x.x; acc[2].y += p0.z * x.y; acc[2].z += p0.z * x.z; acc[2].w += p0.z * x.w;
        acc[3].x += p0.w * x.x; acc[3].y += p0.w * x.y; acc[3].z += p0.w * x.z; acc[3].w += p0.w * x.w;
        acc[4].x += p1.x * x.x; acc[4].y += p1.x * x.y; acc[4].z += p1.x * x.z; acc[4].w += p1.x * x.w;
        acc[5].x += p1.y * x.x; acc[5].y += p1.y * x.y; acc[5].z += p1.y * x.z; acc[5].w += p1.y * x.w;
        acc[6].x += p1.z * x.x; acc[6].y += p1.z * x.y; acc[6].z += p1.z * x.z; acc[6].w += p1.z * x.w;
        acc[7].x += p1.w * x.x; acc[7].y += p1.w * x.y; acc[7].z += p1.w * x.z; acc[7].w += p1.w * x.w;
    }
#pragma unroll
    for (int h = 0; h < NH; h++)
        ((float4*)g_wpart)[(((size_t)(b * NH + h)) * NSCHUNK + scnk) * (HID / 4) + i4] = acc[h];
}

// ---------------------------------------------------------------------------
// Kernel 6: ctx[b, h*96+d] = w[b,h,:] @ Wv[:, h*96+d] + bv
// grid(B, NH), block(384) = 96 j-cols x 4 k-groups of 192 i.
// ---------------------------------------------------------------------------
__global__ void __launch_bounds__(384) k_ctx(const float* __restrict__ Wv,
                                             const float* __restrict__ bv) {
    int b = blockIdx.x, h = blockIdx.y;
    __shared__ float sw[HID];
    __shared__ float part[3][HD];
    size_t wbase = ((size_t)(b * NH + h)) * NSCHUNK * HID;
    for (int i = threadIdx.x; i < HID; i += 384) {
        float a = 0.f;
#pragma unroll
        for (int c = 0; c < NSCHUNK; c++) a += g_wpart[wbase + (size_t)c * HID + i];
        sw[i] = a;
    }
    __syncthreads();
    int j = threadIdx.x % HD, kg = threadIdx.x / HD;  // 96 | 32 -> warps don't split kg
    const float* w = Wv + h * HD + j;
    float acc = 0.f;
    int i0 = kg * 192;
#pragma unroll 8
    for (int i = i0; i < i0 + 192; i++) acc += sw[i] * w[(size_t)i * HID];
    if (kg > 0) part[kg - 1][j] = acc;
    __syncthreads();
    if (kg == 0)
        g_ctx[b * HID + h * HD + j] =
            acc + part[0][j] + part[1][j] + part[2][j] + bv[h * HD + j];
}

// ---------------------------------------------------------------------------
// Kernel 7: out[b,j] = relu(ctx[b,:] @ Wo[:,j] + bo[j])   grid(B), block(128)
// ---------------------------------------------------------------------------
__global__ void __launch_bounds__(128) k_out(const float* __restrict__ Wo,
                                             const float* __restrict__ bo,
                                             float* __restrict__ out) {
    int b = blockIdx.x;
    int warp = threadIdx.x >> 5, lane = threadIdx.x & 31;
    float acc = 0.f;
    for (int i = lane; i < HID; i += 32)
        acc += g_ctx[b * HID + i] * Wo[i * OUTF + warp];
#pragma unroll
    for (int o = 16; o > 0; o >>= 1) acc += __shfl_xor_sync(0xffffffffu, acc, o);
    if (lane == 0) out[b * OUTF + warp] = fmaxf(acc + bo[warp], 0.f);
}

// ---------------------------------------------------------------------------
extern "C" void kernel_launch(void* const* d_in, const int* in_sizes, int n_in,
                              void* d_out, int out_size) {
    const float* X    = (const float*)d_in[0];  // hidden_states (B,S,HID)
    const float* mask = (const float*)d_in[1];  // attention_mask (B,S)
    const float* Wq   = (const float*)d_in[2];
    const float* bq   = (const float*)d_in[3];
    const float* Wk   = (const float*)d_in[4];
    // d_in[5] = bk: provably softmax-invariant (constant per (b,h)), unused
    const float* Wv   = (const float*)d_in[6];
    const float* bv   = (const float*)d_in[7];
    const float* Wo   = (const float*)d_in[8];
    const float* bo   = (const float*)d_in[9];
    float* out = (float*)d_out;
    (void)in_sizes; (void)n_in; (void)out_size;

    dim3 gq(B, 6);
    k_q0<<<gq, 256>>>(X, Wq, bq);
    dim3 gu(NH, 6);
    k_u<<<gu, 128>>>(Wk);
    dim3 gs(S / 32, B);
    k_scores<<<gs, 256>>>(X, mask);
    k_softmax<<<B * NH, 256>>>();
    dim3 gw(B, NSCHUNK);
    k_wsum<<<gw, 192>>>(X);
    dim3 gc(B, NH);
    k_ctx<<<gc, 384>>>(Wv, bv);
    k_out<<<B, 128>>>(Wo, bo, out);
}